// round 6
// baseline (speedup 1.0000x reference)
#include <cuda_runtime.h>
#include <cuda_fp16.h>
#include <cstdint>

// ---------------- problem constants ----------------
#define E_EDGES 65536
#define D_K     200
#define H_N     100
#define T_TYPES 8
#define P_PAIRS 64                      // edge-pairs per CTA
#define NCTA    (E_EDGES / P_PAIRS)     // 1024
#define NTHREADS 256
#define KP      208                     // K padded (13 x k16)
#define NP      104                     // N padded (13 x n8)
#define AROWB   432                     // A row stride bytes, LDSM conflict-free
#define BROWB   208                     // B row stride bytes, LDSM conflict-free
#define A_SZ    (P_PAIRS * AROWB)       // 27648
#define BUFSZ   6656                    // B chunk: 32 k-rows x 208 B

// smem offsets (total 105,792 B -> 2 CTAs/SM)
#define OFF_AS  0
#define OFF_AP  (A_SZ)
#define OFF_AN  (2 * A_SZ)
#define OFF_B0  (3 * A_SZ)              // 82944, 3 buffers
#define OFF_CB  (OFF_B0 + 3 * BUFSZ)    // 102912 (104 f32)
#define OFF_OW  (OFF_CB + NP * 4)       // 103328 (104 f32)
#define OFF_EP  (OFF_OW + NP * 4)       // 103744 (4*64 f32)
#define OFF_EN  (OFF_EP + 256 * 4)      // 104768 (4*64 f32)
#define SMEM_TOTAL (OFF_EN + 256 * 4)   // 105792

// preconverted weights: [mat(2)][t(8)][k(208)][n(104)] fp16, pads zero
__device__ __align__(16) __half g_W16[2 * T_TYPES * KP * NP];

// ---------------- helpers ----------------
__device__ __forceinline__ uint32_t smem_u32(const void* p) {
    uint32_t a;
    asm("{ .reg .u64 t; cvta.to.shared.u64 t, %1; cvt.u32.u64 %0, t; }" : "=r"(a) : "l"(p));
    return a;
}
__device__ __forceinline__ void ldsm_x4(uint32_t* r, uint32_t a) {
    asm volatile("ldmatrix.sync.aligned.m8n8.x4.shared.b16 {%0,%1,%2,%3}, [%4];"
        : "=r"(r[0]), "=r"(r[1]), "=r"(r[2]), "=r"(r[3]) : "r"(a));
}
__device__ __forceinline__ void ldsm_x4t(uint32_t* r, uint32_t a) {
    asm volatile("ldmatrix.sync.aligned.m8n8.x4.trans.shared.b16 {%0,%1,%2,%3}, [%4];"
        : "=r"(r[0]), "=r"(r[1]), "=r"(r[2]), "=r"(r[3]) : "r"(a));
}
__device__ __forceinline__ void ldsm_x2t(uint32_t* r, uint32_t a) {
    asm volatile("ldmatrix.sync.aligned.m8n8.x2.trans.shared.b16 {%0,%1}, [%2];"
        : "=r"(r[0]), "=r"(r[1]) : "r"(a));
}
__device__ __forceinline__ void mma16816(float* c, const uint32_t* a, const uint32_t* b) {
    asm volatile("mma.sync.aligned.m16n8k16.row.col.f32.f16.f16.f32 "
        "{%0,%1,%2,%3}, {%4,%5,%6,%7}, {%8,%9}, {%0,%1,%2,%3};"
        : "+f"(c[0]), "+f"(c[1]), "+f"(c[2]), "+f"(c[3])
        : "r"(a[0]), "r"(a[1]), "r"(a[2]), "r"(a[3]), "r"(b[0]), "r"(b[1]));
}
__device__ __forceinline__ uint32_t pack_h2(float x, float y) {
    __half2 t = __floats2half2_rn(x, y);
    return *reinterpret_cast<uint32_t*>(&t);
}
#define CP_COMMIT() asm volatile("cp.async.commit_group;" ::: "memory")
#define CP_WAIT1()  asm volatile("cp.async.wait_group 1;" ::: "memory")
#define CP_WAIT0()  asm volatile("cp.async.wait_group 0;" ::: "memory")

// stage chunk c (2 k-steps = 32 rows; c==6 -> 1 step = 16 rows) of matrix mt (0..15)
__device__ __forceinline__ void stage_chunk(int mt, int c, uint32_t dst_s, int tid) {
    const char* src = reinterpret_cast<const char*>(g_W16)
                    + ((size_t)mt * KP + (size_t)(32 * c)) * NP * 2;
    const int bytes = (c == 6) ? (16 * BROWB) : (32 * BROWB);
    for (int off = tid * 16; off < bytes; off += NTHREADS * 16)
        asm volatile("cp.async.ca.shared.global [%0], [%1], 16;"
                     :: "r"(dst_s + (uint32_t)off), "l"(src + off) : "memory");
}

// ---------------- prologue: weights -> fp16 [mat][t][k][n], zero-padded ----------------
__global__ void wconv_kernel(const float* __restrict__ srcW, const float* __restrict__ dstW) {
    int i = blockIdx.x * blockDim.x + threadIdx.x;
    const int TOT = 2 * T_TYPES * KP * NP;
    if (i >= TOT) return;
    int n   = i % NP;
    int k   = (i / NP) % KP;
    int t   = (i / (NP * KP)) % T_TYPES;
    int mat = i / (NP * KP * T_TYPES);
    float v = 0.0f;
    if (k < D_K && n < H_N) {
        const float* W = mat ? dstW : srcW;
        v = W[(size_t)t * D_K * H_N + (size_t)k * H_N + n];
    }
    g_W16[i] = __float2half_rn(v);
}

// ---------------- chunk compute ----------------
// src phase: c[r][j] += A_src @ Ws-chunk
template <int NSTEPS, int NBLK>
__device__ __forceinline__ void kseg_src(
    uint32_t a0, uint32_t a1, int s0, uint32_t bb,
    uint32_t rb0, uint32_t rb1, uint32_t rb2,
    float (&c)[2][4][4])
{
#pragma unroll
    for (int ls = 0; ls < NSTEPS; ls++) {
        const uint32_t ka = (uint32_t)(s0 + ls) * 32;
        const uint32_t kb = (uint32_t)ls * 16 * BROWB;
        uint32_t A0[4], A1[4];
        ldsm_x4(A0, a0 + ka);
        ldsm_x4(A1, a1 + ka);
        uint32_t B[8];
        ldsm_x4t(B + 0, bb + rb0 + kb);
        if (NBLK == 4) ldsm_x4t(B + 4, bb + rb1 + kb);
        else           ldsm_x2t(B + 4, bb + rb2 + kb);
#pragma unroll
        for (int j = 0; j < NBLK; j++) {
            mma16816(c[0][j], A0, B + 2 * j);
            mma16816(c[1][j], A1, B + 2 * j);
        }
    }
}

// dst phase: cP += A_pos @ Wd-chunk ; cN += A_neg @ Wd-chunk
template <int NSTEPS, int NBLK>
__device__ __forceinline__ void kseg_dst(
    uint32_t p0, uint32_t p1, uint32_t q0, uint32_t q1, int s0, uint32_t bb,
    uint32_t rb0, uint32_t rb1, uint32_t rb2,
    float (&cP)[2][4][4], float (&cN)[2][4][4])
{
#pragma unroll
    for (int ls = 0; ls < NSTEPS; ls++) {
        const uint32_t ka = (uint32_t)(s0 + ls) * 32;
        const uint32_t kb = (uint32_t)ls * 16 * BROWB;
        uint32_t P0[4], P1[4], Q0[4], Q1[4];
        ldsm_x4(P0, p0 + ka);
        ldsm_x4(P1, p1 + ka);
        ldsm_x4(Q0, q0 + ka);
        ldsm_x4(Q1, q1 + ka);
        uint32_t B[8];
        ldsm_x4t(B + 0, bb + rb0 + kb);
        if (NBLK == 4) ldsm_x4t(B + 4, bb + rb1 + kb);
        else           ldsm_x2t(B + 4, bb + rb2 + kb);
#pragma unroll
        for (int j = 0; j < NBLK; j++) {
            mma16816(cP[0][j], P0, B + 2 * j);
            mma16816(cP[1][j], P1, B + 2 * j);
            mma16816(cN[0][j], Q0, B + 2 * j);
            mma16816(cN[1][j], Q1, B + 2 * j);
        }
    }
}

// ---------------- main fused kernel ----------------
__global__ __launch_bounds__(NTHREADS, 2)
void sthn_hmma_kernel(const float* __restrict__ h,
                      const float* __restrict__ src_b, const float* __restrict__ dst_b,
                      const float* __restrict__ out_W, const float* __restrict__ out_b,
                      const int*   __restrict__ poss,
                      float* __restrict__ out)
{
    extern __shared__ char smem[];
    const uint32_t sb = smem_u32(smem);
    const int tid  = threadIdx.x;
    const int lane = tid & 31;
    const int w    = tid >> 5;
    const int n0   = blockIdx.x * P_PAIRS;

    // kick off first two chunks of Ws(0)
    stage_chunk(0, 0, sb + OFF_B0, tid);            CP_COMMIT();
    stage_chunk(0, 1, sb + OFF_B0 + BUFSZ, tid);    CP_COMMIT();

    // ---- convert the three A tiles fp32 -> fp16 into smem (once) ----
    {
        const int QUADS = KP / 4;   // 52 uint2-stores per row
        for (int idx = tid; idx < 3 * P_PAIRS * QUADS; idx += NTHREADS) {
            int tile = idx / (P_PAIRS * QUADS);
            int rem  = idx - tile * (P_PAIRS * QUADS);
            int row  = rem / QUADS;
            int k    = (rem - row * QUADS) * 4;
            uint2 v16;
            if (k < D_K) {
                const float4 v = *reinterpret_cast<const float4*>(
                    h + (size_t)(tile * E_EDGES + n0 + row) * D_K + k);
                v16.x = pack_h2(v.x, v.y);
                v16.y = pack_h2(v.z, v.w);
            } else { v16.x = 0u; v16.y = 0u; }
            *reinterpret_cast<uint2*>(smem + tile * A_SZ + row * AROWB + k * 2) = v16;
        }
    }

    // ---- per-warp fragment addressing ----
    const int mw = w & 1;               // M-warp: 32 rows (m=2)
    const int ng = w >> 1;              // N-group 0..3
    const int mb = mw * 32;
    const int nbase = (ng == 0) ? 0 : (ng == 1 ? 4 : (ng == 2 ? 7 : 10));
    const int nblk  = (ng == 0) ? 4 : 3;

    const uint32_t aOff0 = (uint32_t)(mb + (lane & 15)) * AROWB + (uint32_t)(lane >> 4) * 16;
    const uint32_t aOff1 = aOff0 + 16u * AROWB;
    const uint32_t aS0 = sb + OFF_AS + aOff0, aS1 = sb + OFF_AS + aOff1;
    const uint32_t aP0 = sb + OFF_AP + aOff0, aP1 = sb + OFF_AP + aOff1;
    const uint32_t aN0 = sb + OFF_AN + aOff0, aN1 = sb + OFF_AN + aOff1;

    const uint32_t bRow = (uint32_t)(lane & 15) * BROWB;
    const uint32_t bSel = (uint32_t)(lane >> 4);
    const uint32_t rb0 = bRow + (uint32_t)(nbase + 0 + bSel) * 16;   // x4t: blocks nbase, nbase+1
    const uint32_t rb1 = bRow + (uint32_t)(nbase + 2 + bSel) * 16;   // x4t: blocks nbase+2,+3
    const uint32_t rb2 = bRow + (uint32_t)(nbase + 2) * 16;          // x2t: block nbase+2

    float* EP = reinterpret_cast<float*>(smem + OFF_EP);
    float* EN = reinterpret_cast<float*>(smem + OFF_EN);
    const float* CB = reinterpret_cast<const float*>(smem + OFF_CB);
    const float* OW = reinterpret_cast<const float*>(smem + OFF_OW);

    float bestP = -1e30f, bestN = -1e30f;
    int   anyP = 0, anyN = 0;

    // stage cursor: next chunk to stage is global segment 2 -> (t=0, phase=0, c=2)
    int ts = 0, ps = 0, cs = 2;
    int bi = 0;   // buffer index of the chunk being computed

    for (int t = 0; t < T_TYPES; t++) {
        float cP[2][4][4], cN[2][4][4];
#pragma unroll
        for (int r = 0; r < 2; r++)
#pragma unroll
            for (int j = 0; j < 4; j++)
#pragma unroll
                for (int q = 0; q < 4; q++) cP[r][j][q] = 0.f;

        for (int seg = 0; seg < 14; seg++) {
            const int phase = seg >= 7;
            const int c     = phase ? seg - 7 : seg;

            CP_WAIT1();            // my chunk(seg)'s cp.async ops complete
            __syncthreads();       // publish chunk(seg); buffer bi+2 free

            // stage chunk at cursor into buffer (bi+2)%3
            {
                int bs = bi + 2; if (bs >= 3) bs -= 3;
                stage_chunk(ps ? 8 + ts : ts, cs, sb + OFF_B0 + (uint32_t)bs * BUFSZ, tid);
                CP_COMMIT();
                if (++cs == 7) { cs = 0; ps ^= 1; if (!ps) ts = (ts + 1) & 7; }
            }
            if (seg == 0 && tid < NP) {   // epilogue constants for this t
                int cc = tid;
                float cb = 0.0f, ow = 0.0f;
                if (cc < H_N) {
                    cb = src_b[t * H_N + cc] + dst_b[t * H_N + cc];
                    ow = out_W[t * H_N + cc];
                }
                reinterpret_cast<float*>(smem + OFF_CB)[cc] = cb;
                reinterpret_cast<float*>(smem + OFF_OW)[cc] = ow;
            }

            const uint32_t bb = sb + OFF_B0 + (uint32_t)bi * BUFSZ;
            const int s0 = 2 * c;
            if (!phase) {
                if (c < 6) {
                    if (ng == 0) kseg_src<2,4>(aS0, aS1, s0, bb, rb0, rb1, rb2, cP);
                    else         kseg_src<2,3>(aS0, aS1, s0, bb, rb0, rb1, rb2, cP);
                } else {
                    if (ng == 0) kseg_src<1,4>(aS0, aS1, s0, bb, rb0, rb1, rb2, cP);
                    else         kseg_src<1,3>(aS0, aS1, s0, bb, rb0, rb1, rb2, cP);
                    // src contribution shared by pos & neg
#pragma unroll
                    for (int r = 0; r < 2; r++)
#pragma unroll
                        for (int j = 0; j < 4; j++)
#pragma unroll
                            for (int q = 0; q < 4; q++) cN[r][j][q] = cP[r][j][q];
                }
            } else {
                if (c < 6) {
                    if (ng == 0) kseg_dst<2,4>(aP0, aP1, aN0, aN1, s0, bb, rb0, rb1, rb2, cP, cN);
                    else         kseg_dst<2,3>(aP0, aP1, aN0, aN1, s0, bb, rb0, rb1, rb2, cP, cN);
                } else {
                    if (ng == 0) kseg_dst<1,4>(aP0, aP1, aN0, aN1, s0, bb, rb0, rb1, rb2, cP, cN);
                    else         kseg_dst<1,3>(aP0, aP1, aN0, aN1, s0, bb, rb0, rb1, rb2, cP, cN);
                }
            }
            if (++bi == 3) bi = 0;
        }

        // ---- epilogue: relu + out_W dot, quad-reduce, masked max ----
#pragma unroll
        for (int r = 0; r < 2; r++) {
            float pP0 = 0.f, pP1 = 0.f, pN0 = 0.f, pN1 = 0.f;
            for (int j = 0; j < nblk; j++) {
                const int c0 = (nbase + j) * 8 + (lane & 3) * 2;
                const float cb0 = CB[c0], cb1 = CB[c0 + 1];
                const float ow0 = OW[c0], ow1 = OW[c0 + 1];
                pP0 += fmaxf(cP[r][j][0] + cb0, 0.f) * ow0 + fmaxf(cP[r][j][1] + cb1, 0.f) * ow1;
                pP1 += fmaxf(cP[r][j][2] + cb0, 0.f) * ow0 + fmaxf(cP[r][j][3] + cb1, 0.f) * ow1;
                pN0 += fmaxf(cN[r][j][0] + cb0, 0.f) * ow0 + fmaxf(cN[r][j][1] + cb1, 0.f) * ow1;
                pN1 += fmaxf(cN[r][j][2] + cb0, 0.f) * ow0 + fmaxf(cN[r][j][3] + cb1, 0.f) * ow1;
            }
#pragma unroll
            for (int off = 1; off <= 2; off <<= 1) {
                pP0 += __shfl_xor_sync(0xffffffffu, pP0, off);
                pP1 += __shfl_xor_sync(0xffffffffu, pP1, off);
                pN0 += __shfl_xor_sync(0xffffffffu, pN0, off);
                pN1 += __shfl_xor_sync(0xffffffffu, pN1, off);
            }
            if ((lane & 3) == 0) {
                const int r0 = mb + 16 * r + (lane >> 2);
                EP[ng * P_PAIRS + r0] = pP0;  EP[ng * P_PAIRS + r0 + 8] = pP1;
                EN[ng * P_PAIRS + r0] = pN0;  EN[ng * P_PAIRS + r0 + 8] = pN1;
            }
        }
        __syncthreads();

        if (tid < P_PAIRS) {
            const float ob = out_b[t];
            const float sp = EP[tid] + EP[P_PAIRS + tid] + EP[2 * P_PAIRS + tid]
                           + EP[3 * P_PAIRS + tid] + ob;
            const float sn = EN[tid] + EN[P_PAIRS + tid] + EN[2 * P_PAIRS + tid]
                           + EN[3 * P_PAIRS + tid] + ob;
            if (poss[(size_t)(n0 + tid) * T_TYPES + t] != 0)           { bestP = fmaxf(bestP, sp); anyP = 1; }
            if (poss[(size_t)(E_EDGES + n0 + tid) * T_TYPES + t] != 0) { bestN = fmaxf(bestN, sn); anyN = 1; }
        }
        // EP/EN are rewritten only after the next t's 14 segment barriers - safe
    }

    CP_WAIT0();   // drain trailing prefetches

    if (tid < P_PAIRS) {
        out[n0 + tid]           = anyP ? bestP : 0.0f;
        out[E_EDGES + n0 + tid] = anyN ? bestN : 0.0f;
    }
}

// ---------------- launch ----------------
extern "C" void kernel_launch(void* const* d_in, const int* in_sizes, int n_in,
                              void* d_out, int out_size)
{
    const float* h      = (const float*)d_in[0];
    const float* src_W  = (const float*)d_in[1];
    const float* src_b  = (const float*)d_in[2];
    const float* dst_W  = (const float*)d_in[3];
    const float* dst_b  = (const float*)d_in[4];
    const float* out_W  = (const float*)d_in[5];
    const float* out_b  = (const float*)d_in[6];
    const int*   poss   = (const int*)d_in[7];
    float*       out    = (float*)d_out;

    cudaFuncSetAttribute(sthn_hmma_kernel,
                         cudaFuncAttributeMaxDynamicSharedMemorySize, SMEM_TOTAL);

    const int wtot = 2 * T_TYPES * KP * NP;
    wconv_kernel<<<(wtot + 255) / 256, 256>>>(src_W, dst_W);
    sthn_hmma_kernel<<<NCTA, NTHREADS, SMEM_TOTAL>>>(h, src_b, dst_b, out_W, out_b, poss, out);
}